// round 16
// baseline (speedup 1.0000x reference)
#include <cuda_runtime.h>
#include <cuda_fp16.h>
#include <cstdint>

// B=2, S=2048, D=768, H=12, DH=64
#define SB 2
#define SS 2048
#define SD 768
#define SH 12
#define SDH 64

// ---------------------------------------------------------------------------
// Scratch (static device globals — no allocations allowed). fp16 pipeline.
// ---------------------------------------------------------------------------
__device__ __half g_in[3][4096*768];     // q,k,v inputs fp16
__device__ __half g_w[4][768*768];       // Wq,Wk,Wv,Wo fp16
__device__ __half g_q[SB*SH*SS*SDH];     // projected q (PRE-SCALED by 0.125*log2e)
__device__ __half g_k[SB*SH*SS*SDH];
__device__ __half g_v[SB*SH*SS*SDH];
__device__ __half g_att[4096*768];       // attention output fp16
__device__ __half g_mask[SS*SS];         // mask fp16 (PRE-SCALED by 0.125*log2e)

#define SCL 0.180336880f               // 0.125 * log2(e)

// ---------------------------------------------------------------------------
__device__ __forceinline__ uint32_t smem_u32(const void* p) {
    uint32_t a;
    asm("{ .reg .u64 t; cvta.to.shared.u64 t, %1; cvt.u32.u64 %0, t; }"
        : "=r"(a) : "l"(p));
    return a;
}

#define LDSM_X4(r0, r1, r2, r3, addr) \
    asm volatile("ldmatrix.sync.aligned.m8n8.x4.shared.b16 {%0,%1,%2,%3}, [%4];" \
        : "=r"(r0), "=r"(r1), "=r"(r2), "=r"(r3) : "r"(addr))

#define LDSM_X4_T(r0, r1, r2, r3, addr) \
    asm volatile("ldmatrix.sync.aligned.m8n8.x4.trans.shared.b16 {%0,%1,%2,%3}, [%4];" \
        : "=r"(r0), "=r"(r1), "=r"(r2), "=r"(r3) : "r"(addr))

#define MMA_F16(d, a, b) \
    asm volatile("mma.sync.aligned.m16n8k16.row.col.f32.f16.f16.f32 " \
        "{%0,%1,%2,%3}, {%4,%5,%6,%7}, {%8,%9}, {%0,%1,%2,%3};" \
        : "+f"((d)[0]), "+f"((d)[1]), "+f"((d)[2]), "+f"((d)[3]) \
        : "r"((a)[0]), "r"((a)[1]), "r"((a)[2]), "r"((a)[3]), \
          "r"((b)[0]), "r"((b)[1]))

#define CP_ASYNC16(s, g) \
    asm volatile("cp.async.cg.shared.global [%0], [%1], 16;" :: "r"(s), "l"(g))
#define CP_COMMIT() asm volatile("cp.async.commit_group;" ::: "memory")
#define CP_WAIT0()  asm volatile("cp.async.wait_group 0;" ::: "memory")

__device__ __forceinline__ uint32_t hpack(float a, float b) {
    __half2 t = __floats2half2_rn(a, b);
    return *reinterpret_cast<uint32_t*>(&t);
}

// fp16x2 exp2: pack two fp32 exponents -> half2 -> ex2.approx.f16x2.
__device__ __forceinline__ uint32_t hexp2_pack(float a, float b) {
    uint32_t x = hpack(a, b);
    asm("ex2.approx.f16x2 %0, %0;" : "+r"(x));
    return x;
}

// ---------------------------------------------------------------------------
// fp32 -> fp16 conversion: ALL tensors in ONE launch (flat block ranges).
// ---------------------------------------------------------------------------
__global__ __launch_bounds__(256) void conv_all(
    const float* __restrict__ q, const float* __restrict__ k,
    const float* __restrict__ v,
    const float* __restrict__ w0, const float* __restrict__ w1,
    const float* __restrict__ w2, const float* __restrict__ w3,
    const float* __restrict__ m)
{
    const int blk = blockIdx.x;
    const float* src;
    __half* dst;
    int base;
    float scl = 1.0f;
    if (blk < 9216) {
        const int idx = blk / 3072;
        base = blk % 3072;
        src = (idx == 0) ? q : (idx == 1) ? k : v;
        dst = g_in[idx];
    } else if (blk < 11520) {
        const int r = blk - 9216;
        const int idx = r / 576;
        base = r % 576;
        src = (idx == 0) ? w0 : (idx == 1) ? w1 : (idx == 2) ? w2 : w3;
        dst = g_w[idx];
    } else {
        base = blk - 11520;
        src = m;
        dst = g_mask;
        scl = SCL;
    }
    const int i = (base * 256 + threadIdx.x) * 4;
    float4 vv = *(const float4*)(src + i);
    *(__half2*)(dst + i)     = __floats2half2_rn(vv.x * scl, vv.y * scl);
    *(__half2*)(dst + i + 2) = __floats2half2_rn(vv.z * scl, vv.w * scl);
}

// ---------------------------------------------------------------------------
// Shared 64x128 GEMM building block: CTA 64(m) x 128(n), 128 threads,
// 4 warps of 32x64, cp.async double buffer, occ 4.  (validated on gemm_out)
// ---------------------------------------------------------------------------
#define SO_BIAS 0
#define SO_BUF  1024                  // + buf*24576 : A 8K + B 16K
#define SO_TOT  (1024 + 2 * 24576)    // 50176

__device__ __forceinline__ void g64_load_chunk(
    uint32_t sb, int tid, const __half* __restrict__ A,
    const __half* __restrict__ B, int m0, int n0, int c, int buf)
{
    const uint32_t kb = SO_BUF + (uint32_t)buf * 24576u;
    const int k0 = c << 6;
    #pragma unroll
    for (int r = 0; r < 4; ++r) {       // A: 64 rows x 8 units = 512
        const int u = r * 128 + tid;
        const int row = u >> 3, c16 = u & 7;
        const uint32_t so = (uint32_t)(row * 128 + ((c16 * 16) ^ ((row & 7) << 4)));
        CP_ASYNC16(sb + kb + so,
                   (const char*)(A + (size_t)(m0 + row) * 768 + k0 + c16 * 8));
    }
    #pragma unroll
    for (int r = 0; r < 8; ++r) {       // B: 128 rows x 8 units = 1024
        const int u = r * 128 + tid;
        const int row = u >> 3, c16 = u & 7;
        const uint32_t so = (uint32_t)(row * 128 + ((c16 * 16) ^ ((row & 7) << 4)));
        CP_ASYNC16(sb + kb + 8192 + so,
                   (const char*)(B + (size_t)(n0 + row) * 768 + k0 + c16 * 8));
    }
}

// Mainloop: accumulates acc[2][8][4] for a 64x128 tile. Shared by both GEMMs.
__device__ __forceinline__ void g64_mainloop(
    uint32_t sb, int tid, const __half* __restrict__ A,
    const __half* __restrict__ B, int m0, int n0, float acc[2][8][4])
{
    const int wid = tid >> 5;
    const int lid = tid & 31;
    const int wm = (wid >> 1) << 5;     // 0/32
    const int wn = (wid & 1) << 6;      // 0/64
    const int lq = lid >> 3;
    const int lr = lid & 7;

    for (int c = 0; c < 12; ++c) {
        CP_WAIT0();
        __syncthreads();
        if (c < 11) {
            g64_load_chunk(sb, tid, A, B, m0, n0, c + 1, (c + 1) & 1);
            CP_COMMIT();
        }
        const uint32_t kb = SO_BUF + (uint32_t)(c & 1) * 24576u;

        #pragma unroll
        for (int ks = 0; ks < 4; ++ks) {
            uint32_t ah[2][4];
            #pragma unroll
            for (int mt = 0; mt < 2; ++mt) {
                const int row = wm + mt * 16 + ((lq & 1) << 3) + lr;
                const int kc  = (ks << 4) + ((lq >> 1) << 3);
                const uint32_t off = (uint32_t)(row * 128 + ((kc * 2) ^ ((row & 7) << 4)));
                LDSM_X4(ah[mt][0], ah[mt][1], ah[mt][2], ah[mt][3], sb + kb + off);
            }
            uint32_t bh[8][2];
            #pragma unroll
            for (int nf = 0; nf < 4; ++nf) {
                const int nrow = wn + nf * 16 + ((lq >> 1) << 3) + lr;
                const int kc   = (ks << 4) + ((lq & 1) << 3);
                const uint32_t off = (uint32_t)(nrow * 128 + ((kc * 2) ^ ((nrow & 7) << 4)));
                uint32_t t0, t1, t2, t3;
                LDSM_X4(t0, t1, t2, t3, sb + kb + 8192 + off);
                bh[nf * 2][0] = t0;     bh[nf * 2][1] = t1;
                bh[nf * 2 + 1][0] = t2; bh[nf * 2 + 1][1] = t3;
            }
            #pragma unroll
            for (int mt = 0; mt < 2; ++mt)
                #pragma unroll
                for (int nt = 0; nt < 8; ++nt)
                    MMA_F16(acc[mt][nt], ah[mt], bh[nt]);
        }
    }
}

// ---------------------------------------------------------------------------
// QKV projection: 64x128 tiles, grid (64, 6, 3), occ 4. Scatter + q prescale.
// ---------------------------------------------------------------------------
__global__ __launch_bounds__(128, 4) void gemm_qkv(const float* __restrict__ bq,
                                                   const float* __restrict__ bk,
                                                   const float* __restrict__ bv)
{
    extern __shared__ __align__(1024) char smem[];
    const int z = blockIdx.z;
    const float* bias = (z == 0) ? bq : (z == 1) ? bk : bv;
    __half* dst = (z == 0) ? g_q : (z == 1) ? g_k : g_v;
    const float oscale = (z == 0) ? SCL : 1.0f;
    const __half* A = g_in[z];
    const __half* B = g_w[z];
    const int m0 = blockIdx.x << 6;
    const int n0 = blockIdx.y << 7;
    const int tid = threadIdx.x;
    const int wid = tid >> 5;
    const int lid = tid & 31;
    const uint32_t sb = smem_u32(smem);

    if (tid < 32)
        ((float4*)(smem + SO_BIAS))[tid] = ((const float4*)(bias + n0))[tid];

    g64_load_chunk(sb, tid, A, B, m0, n0, 0, 0);
    CP_COMMIT();

    float acc[2][8][4];
    #pragma unroll
    for (int mt = 0; mt < 2; ++mt)
        #pragma unroll
        for (int nt = 0; nt < 8; ++nt)
            #pragma unroll
            for (int e = 0; e < 4; ++e) acc[mt][nt][e] = 0.f;

    g64_mainloop(sb, tid, A, B, m0, n0, acc);

    const int wm = (wid >> 1) << 5;
    const int wn = (wid & 1) << 6;
    const int gID = lid >> 2;
    const int tc  = (lid & 3) << 1;
    const float* bs = (const float*)(smem + SO_BIAS);
    #pragma unroll
    for (int mt = 0; mt < 2; ++mt)
        #pragma unroll
        for (int nt = 0; nt < 8; ++nt) {
            const int colr = wn + nt * 8 + tc;
            const float b0 = bs[colr], b1 = bs[colr + 1];
            #pragma unroll
            for (int rh = 0; rh < 2; ++rh) {
                const int m = m0 + wm + mt * 16 + gID + rh * 8;
                float rx = (acc[mt][nt][rh * 2 + 0] + b0) * oscale;
                float ry = (acc[mt][nt][rh * 2 + 1] + b1) * oscale;
                const int b = m >> 11;
                const int s = m & 2047;
                const int head = (n0 + colr) >> 6;
                const int dh   = (n0 + colr) & 63;
                const size_t o = ((size_t)((b * 12 + head) << 11) + s) * 64 + dh;
                *(__half2*)(dst + o) = __floats2half2_rn(rx, ry);
            }
        }
}

// ---------------------------------------------------------------------------
// OUT GEMM: 64x128 tiles, grid (64, 6), occ 4. fp32 store. (R14/R15, 20.1us)
// ---------------------------------------------------------------------------
__global__ __launch_bounds__(128, 4) void gemm_out(const float* __restrict__ bo,
                                                   float* __restrict__ out)
{
    extern __shared__ __align__(1024) char smem[];
    const int m0 = blockIdx.x << 6;
    const int n0 = blockIdx.y << 7;
    const int tid = threadIdx.x;
    const int wid = tid >> 5;
    const int lid = tid & 31;
    const uint32_t sb = smem_u32(smem);

    if (tid < 32)
        ((float4*)(smem + SO_BIAS))[tid] = ((const float4*)(bo + n0))[tid];

    g64_load_chunk(sb, tid, g_att, g_w[3], m0, n0, 0, 0);
    CP_COMMIT();

    float acc[2][8][4];
    #pragma unroll
    for (int mt = 0; mt < 2; ++mt)
        #pragma unroll
        for (int nt = 0; nt < 8; ++nt)
            #pragma unroll
            for (int e = 0; e < 4; ++e) acc[mt][nt][e] = 0.f;

    g64_mainloop(sb, tid, g_att, g_w[3], m0, n0, acc);

    const int wm = (wid >> 1) << 5;
    const int wn = (wid & 1) << 6;
    const int gID = lid >> 2;
    const int tc  = (lid & 3) << 1;
    const float* bs = (const float*)(smem + SO_BIAS);
    #pragma unroll
    for (int mt = 0; mt < 2; ++mt)
        #pragma unroll
        for (int nt = 0; nt < 8; ++nt) {
            const int colr = wn + nt * 8 + tc;
            const float b0 = bs[colr], b1 = bs[colr + 1];
            #pragma unroll
            for (int rh = 0; rh < 2; ++rh) {
                const int m = m0 + wm + mt * 16 + gID + rh * 8;
                float rx = acc[mt][nt][rh * 2 + 0] + b0;
                float ry = acc[mt][nt][rh * 2 + 1] + b1;
                *(float2*)&out[(size_t)m * 768 + n0 + colr] = make_float2(rx, ry);
            }
        }
}

// ---------------------------------------------------------------------------
// Flash attention on HMMA (fp16, fp32 accum). EXACT R13/R15 body.
// CTA: 128 q-rows; 4 warps x 32 rows. Key tiles of 64, double-buffered K/V.
// S init from pre-scaled mask; P via ex2.approx.f16x2; l via ones-MMA.
// 48KB smem, 3 CTAs/SM.
// ---------------------------------------------------------------------------
#define FS_Q   0                     // 16KB: 128 rows x 128B
#define FS_KV  16384                 // + buf*16384 : K 8KB + V 8KB
#define FS_TOT (16384 + 2 * 16384)   // 49152

__device__ __forceinline__ void fa_load_tile(uint32_t sb, int tid, size_t base,
                                             int t, int buf) {
    const uint32_t kb = FS_KV + (uint32_t)buf * 16384u;
    const int s0 = t << 6;
    #pragma unroll
    for (int r = 0; r < 4; ++r) {
        const int u = r * 128 + tid;        // 0..511
        const int row = u >> 3, c16 = u & 7;
        const uint32_t so = (uint32_t)(row * 128 + ((c16 * 16) ^ ((row & 7) << 4)));
        const size_t g = base + (size_t)(s0 + row) * 64 + c16 * 8;
        CP_ASYNC16(sb + kb + so,        (const char*)(g_k + g));
        CP_ASYNC16(sb + kb + 8192 + so, (const char*)(g_v + g));
    }
}

__global__ __launch_bounds__(128, 3) void flash_mma()
{
    extern __shared__ __align__(1024) char smem[];
    const uint32_t sb = smem_u32(smem);
    const int tid = threadIdx.x;
    const int wid = tid >> 5;             // 0..3
    const int lid = tid & 31;
    const int lq  = lid >> 3;
    const int lr  = lid & 7;
    const int q0  = blockIdx.x << 7;      // 128 q-rows per CTA
    const int bh  = blockIdx.y;
    const size_t base = (size_t)bh * SS * SDH;

    // prologue: Q tile (128 rows) + KV tile 0
    #pragma unroll
    for (int r = 0; r < 8; ++r) {
        const int u = r * 128 + tid;      // 0..1023
        const int row = u >> 3, c16 = u & 7;
        const uint32_t so = (uint32_t)(row * 128 + ((c16 * 16) ^ ((row & 7) << 4)));
        CP_ASYNC16(sb + FS_Q + so,
                   (const char*)(g_q + base + (size_t)(q0 + row) * 64 + c16 * 8));
    }
    fa_load_tile(sb, tid, base, 0, 0);
    CP_COMMIT();

    // all-ones fp16 B fragment (1.0h = 0x3C00) for the row-sum MMA
    const uint32_t ones[2] = {0x3C003C00u, 0x3C003C00u};

    float ol[2][4];                       // row-sum accumulators (every col = l)
    float o[2][8][4];
    #pragma unroll
    for (int mt = 0; mt < 2; ++mt) {
        #pragma unroll
        for (int e = 0; e < 4; ++e) ol[mt][e] = 0.f;
        #pragma unroll
        for (int d = 0; d < 8; ++d)
            #pragma unroll
            for (int e = 0; e < 4; ++e) o[mt][d][e] = 0.f;
    }

    const int rA = q0 + (wid << 5) + (lid >> 2);

    for (int t = 0; t < 32; ++t) {
        CP_WAIT0();
        __syncthreads();

        if (t < 31) {
            fa_load_tile(sb, tid, base, t + 1, (t + 1) & 1);
            CP_COMMIT();
        }

        const uint32_t kb = FS_KV + (uint32_t)(t & 1) * 16384u;

        // ---- init S from pre-scaled mask (LDGs issued before MMA chain) ----
        float s_[2][8][4];
        {
            const __half* mk0 = g_mask + (size_t)rA * SS + (t << 6) + ((lid & 3) << 1);
            #pragma unroll
            for (int mt = 0; mt < 2; ++mt) {
                const __half* mlo = mk0 + (size_t)(mt << 4) * SS;
                const __half* mhi = mlo + (size_t)8 * SS;
                #pragma unroll
                for (int nt = 0; nt < 8; ++nt) {
                    float2 ma = __half22float2(*(const __half2*)(mlo + nt * 8));
                    float2 mb = __half22float2(*(const __half2*)(mhi + nt * 8));
                    s_[mt][nt][0] = ma.x; s_[mt][nt][1] = ma.y;
                    s_[mt][nt][2] = mb.x; s_[mt][nt][3] = mb.y;
                }
            }
        }

        // ---- S += Q' K^T (q pre-scaled), 64 keys, 2 m-tiles per warp ----
        #pragma unroll
        for (int ks = 0; ks < 4; ++ks) {
            uint32_t qf[2][4];
            #pragma unroll
            for (int mt = 0; mt < 2; ++mt) {
                const int row = (wid << 5) + (mt << 4) + ((lq & 1) << 3) + lr;
                const int kc  = (ks << 4) + ((lq >> 1) << 3);
                const uint32_t off = (uint32_t)(row * 128 + ((kc * 2) ^ ((row & 7) << 4)));
                LDSM_X4(qf[mt][0], qf[mt][1], qf[mt][2], qf[mt][3], sb + FS_Q + off);
            }
            #pragma unroll
            for (int hf = 0; hf < 4; ++hf) {
                const int nrow = (hf << 4) + ((lq >> 1) << 3) + lr;
                const int kc   = (ks << 4) + ((lq & 1) << 3);
                const uint32_t off = (uint32_t)(nrow * 128 + ((kc * 2) ^ ((nrow & 7) << 4)));
                uint32_t a0, a1, a2, a3;
                LDSM_X4(a0, a1, a2, a3, sb + kb + off);
                uint32_t k0[2] = {a0, a1}, k1[2] = {a2, a3};
                MMA_F16(s_[0][hf * 2],     qf[0], k0);
                MMA_F16(s_[0][hf * 2 + 1], qf[0], k1);
                MMA_F16(s_[1][hf * 2],     qf[1], k0);
                MMA_F16(s_[1][hf * 2 + 1], qf[1], k1);
            }
        }

        // ---- O += P V ; l += P * 1. P = ex2.f16x2(pack(s)) ----
        #pragma unroll
        for (int ks = 0; ks < 4; ++ks) {
            uint32_t ph0[4], ph1[4];
            ph0[0] = hexp2_pack(s_[0][2 * ks][0],     s_[0][2 * ks][1]);
            ph0[1] = hexp2_pack(s_[0][2 * ks][2],     s_[0][2 * ks][3]);
            ph0[2] = hexp2_pack(s_[0][2 * ks + 1][0], s_[0][2 * ks + 1][1]);
            ph0[3] = hexp2_pack(s_[0][2 * ks + 1][2], s_[0][2 * ks + 1][3]);
            ph1[0] = hexp2_pack(s_[1][2 * ks][0],     s_[1][2 * ks][1]);
            ph1[1] = hexp2_pack(s_[1][2 * ks][2],     s_[1][2 * ks][3]);
            ph1[2] = hexp2_pack(s_[1][2 * ks + 1][0], s_[1][2 * ks + 1][1]);
            ph1[3] = hexp2_pack(s_[1][2 * ks + 1][2], s_[1][2 * ks + 1][3]);

            MMA_F16(ol[0], ph0, ones);
            MMA_F16(ol[1], ph1, ones);

            #pragma unroll
            for (int dp = 0; dp < 4; ++dp) {
                const int j = (ks << 4) + ((lq & 1) << 3) + lr;
                const int d = (dp << 4) + ((lq >> 1) << 3);
                const uint32_t off = (uint32_t)(j * 128 + ((d * 2) ^ ((j & 7) << 4)));
                uint32_t v0, v1, v2, v3;
                LDSM_X4_T(v0, v1, v2, v3, sb + kb + 8192 + off);
                uint32_t vf0[2] = {v0, v1}, vf1[2] = {v2, v3};
                MMA_F16(o[0][dp * 2],     ph0, vf0);
                MMA_F16(o[0][dp * 2 + 1], ph0, vf1);
                MMA_F16(o[1][dp * 2],     ph1, vf0);
                MMA_F16(o[1][dp * 2 + 1], ph1, vf1);
            }
        }
    }

    // ---- epilogue: normalize by ones-MMA row sums, fp16 store ----
    const int b = bh / 12;
    const int h = bh % 12;
    #pragma unroll
    for (int mt = 0; mt < 2; ++mt) {
        const float inv0 = 1.f / ol[mt][0];   // rows r: every col equals l
        const float inv1 = 1.f / ol[mt][2];   // rows r+8
        const int s0 = q0 + (wid << 5) + (mt << 4) + (lid >> 2);
        const int s1 = s0 + 8;
        #pragma unroll
        for (int dp = 0; dp < 8; ++dp) {
            const int d = dp * 8 + ((lid & 3) << 1);
            const size_t oa = ((size_t)(b * SS + s0)) * SD + h * 64 + d;
            const size_t ob = ((size_t)(b * SS + s1)) * SD + h * 64 + d;
            *(__half2*)(g_att + oa) =
                __floats2half2_rn(o[mt][dp][0] * inv0, o[mt][dp][1] * inv0);
            *(__half2*)(g_att + ob) =
                __floats2half2_rn(o[mt][dp][2] * inv1, o[mt][dp][3] * inv1);
        }
    }
}

// ---------------------------------------------------------------------------
extern "C" void kernel_launch(void* const* d_in, const int* in_sizes, int n_in,
                              void* d_out, int out_size)
{
    const float* q    = (const float*)d_in[0];
    const float* k    = (const float*)d_in[1];
    const float* v    = (const float*)d_in[2];
    const float* mask = (const float*)d_in[3];
    const float* Wq   = (const float*)d_in[4];
    const float* bq   = (const float*)d_in[5];
    const float* Wk   = (const float*)d_in[6];
    const float* bk   = (const float*)d_in[7];
    const float* Wv   = (const float*)d_in[8];
    const float* bv   = (const float*)d_in[9];
    const float* Wo   = (const float*)d_in[10];
    const float* bo   = (const float*)d_in[11];
    float* out = (float*)d_out;

    (void)in_sizes; (void)n_in; (void)out_size;

    cudaFuncSetAttribute(gemm_qkv, cudaFuncAttributeMaxDynamicSharedMemorySize, SO_TOT);
    cudaFuncSetAttribute(gemm_out, cudaFuncAttributeMaxDynamicSharedMemorySize, SO_TOT);
    cudaFuncSetAttribute(flash_mma, cudaFuncAttributeMaxDynamicSharedMemorySize, FS_TOT);

    conv_all<<<15616, 256>>>(q, k, v, Wq, Wk, Wv, Wo, mask);

    // QKV: 64x128 tiles, 1152 CTAs, occ 4 (validated recipe from gemm_out)
    gemm_qkv<<<dim3(64, 6, 3), 128, SO_TOT>>>(bq, bk, bv);
    flash_mma<<<dim3(SS / 128, SB * SH), 128, FS_TOT>>>();
    gemm_out<<<dim3(64, 6), 128, SO_TOT>>>(bo, out);
}

// round 17
// speedup vs baseline: 1.0288x; 1.0288x over previous
#include <cuda_runtime.h>
#include <cuda_fp16.h>
#include <cstdint>

// B=2, S=2048, D=768, H=12, DH=64
#define SB 2
#define SS 2048
#define SD 768
#define SH 12
#define SDH 64

// ---------------------------------------------------------------------------
// Scratch (static device globals — no allocations allowed). fp16 pipeline.
// ---------------------------------------------------------------------------
__device__ __half g_in[3][4096*768];     // q,k,v inputs fp16
__device__ __half g_w[4][768*768];       // Wq,Wk,Wv,Wo fp16
__device__ __half g_q[SB*SH*SS*SDH];     // projected q (PRE-SCALED by 0.125*log2e)
__device__ __half g_k[SB*SH*SS*SDH];
__device__ __half g_v[SB*SH*SS*SDH];
__device__ __half g_att[4096*768];       // attention output fp16
__device__ __half g_mask[SS*SS];         // mask fp16 (PRE-SCALED by 0.125*log2e)

#define SCL 0.180336880f               // 0.125 * log2(e)

// ---------------------------------------------------------------------------
__device__ __forceinline__ uint32_t smem_u32(const void* p) {
    uint32_t a;
    asm("{ .reg .u64 t; cvta.to.shared.u64 t, %1; cvt.u32.u64 %0, t; }"
        : "=r"(a) : "l"(p));
    return a;
}

#define LDSM_X4(r0, r1, r2, r3, addr) \
    asm volatile("ldmatrix.sync.aligned.m8n8.x4.shared.b16 {%0,%1,%2,%3}, [%4];" \
        : "=r"(r0), "=r"(r1), "=r"(r2), "=r"(r3) : "r"(addr))

#define LDSM_X4_T(r0, r1, r2, r3, addr) \
    asm volatile("ldmatrix.sync.aligned.m8n8.x4.trans.shared.b16 {%0,%1,%2,%3}, [%4];" \
        : "=r"(r0), "=r"(r1), "=r"(r2), "=r"(r3) : "r"(addr))

#define MMA_F16(d, a, b) \
    asm volatile("mma.sync.aligned.m16n8k16.row.col.f32.f16.f16.f32 " \
        "{%0,%1,%2,%3}, {%4,%5,%6,%7}, {%8,%9}, {%0,%1,%2,%3};" \
        : "+f"((d)[0]), "+f"((d)[1]), "+f"((d)[2]), "+f"((d)[3]) \
        : "r"((a)[0]), "r"((a)[1]), "r"((a)[2]), "r"((a)[3]), \
          "r"((b)[0]), "r"((b)[1]))

#define CP_ASYNC16(s, g) \
    asm volatile("cp.async.cg.shared.global [%0], [%1], 16;" :: "r"(s), "l"(g))
#define CP_COMMIT() asm volatile("cp.async.commit_group;" ::: "memory")
#define CP_WAIT0()  asm volatile("cp.async.wait_group 0;" ::: "memory")

__device__ __forceinline__ uint32_t hpack(float a, float b) {
    __half2 t = __floats2half2_rn(a, b);
    return *reinterpret_cast<uint32_t*>(&t);
}

// fp16x2 exp2: pack two fp32 exponents -> half2 -> ex2.approx.f16x2.
__device__ __forceinline__ uint32_t hexp2_pack(float a, float b) {
    uint32_t x = hpack(a, b);
    asm("ex2.approx.f16x2 %0, %0;" : "+r"(x));
    return x;
}

// ---------------------------------------------------------------------------
// fp32 -> fp16 conversion, ONE launch, 16 elems/thread (MLP=4).
// Block ranges (4096 elems per block):
//   [0,2304)     inputs q/k/v (768 blocks each)
//   [2304,2880)  weights      (144 blocks each)
//   [2880,3904)  mask         (1024 blocks, scaled by SCL)
// ---------------------------------------------------------------------------
__global__ __launch_bounds__(256) void conv_all(
    const float* __restrict__ q, const float* __restrict__ k,
    const float* __restrict__ v,
    const float* __restrict__ w0, const float* __restrict__ w1,
    const float* __restrict__ w2, const float* __restrict__ w3,
    const float* __restrict__ m)
{
    const int blk = blockIdx.x;
    const float* src;
    __half* dst;
    int base;
    float scl = 1.0f;
    if (blk < 2304) {
        const int idx = blk / 768;
        base = blk % 768;
        src = (idx == 0) ? q : (idx == 1) ? k : v;
        dst = g_in[idx];
    } else if (blk < 2880) {
        const int r = blk - 2304;
        const int idx = r / 144;
        base = r % 144;
        src = (idx == 0) ? w0 : (idx == 1) ? w1 : (idx == 2) ? w2 : w3;
        dst = g_w[idx];
    } else {
        base = blk - 2880;
        src = m;
        dst = g_mask;
        scl = SCL;
    }
    const int i0 = base * 4096 + threadIdx.x * 4;
    // 4 independent fully-coalesced float4 loads -> MLP 4 hides DRAM latency
    float4 v0 = *(const float4*)(src + i0);
    float4 v1 = *(const float4*)(src + i0 + 1024);
    float4 v2 = *(const float4*)(src + i0 + 2048);
    float4 v3 = *(const float4*)(src + i0 + 3072);
    uint2 o0, o1, o2, o3;
    o0.x = hpack(v0.x * scl, v0.y * scl);  o0.y = hpack(v0.z * scl, v0.w * scl);
    o1.x = hpack(v1.x * scl, v1.y * scl);  o1.y = hpack(v1.z * scl, v1.w * scl);
    o2.x = hpack(v2.x * scl, v2.y * scl);  o2.y = hpack(v2.z * scl, v2.w * scl);
    o3.x = hpack(v3.x * scl, v3.y * scl);  o3.y = hpack(v3.z * scl, v3.w * scl);
    *(uint2*)(dst + i0)        = o0;
    *(uint2*)(dst + i0 + 1024) = o1;
    *(uint2*)(dst + i0 + 2048) = o2;
    *(uint2*)(dst + i0 + 3072) = o3;
}

// ---------------------------------------------------------------------------
// QKV GEMM (fp16): R15 version. CTA 128x128, 256 threads, 8 warps of 32x64.
// K chunks of 64, cp.async double buffer, occ 2.
// ---------------------------------------------------------------------------
#define SM_BIAS 0
#define SM_BUF  1024                  // + buf*32768 : A 16K + B 16K
#define SM_TOT  (1024 + 2 * 32768)    // 66560

__device__ __forceinline__ void gemm_load_chunk(
    uint32_t sb, int tid, const __half* __restrict__ A,
    const __half* __restrict__ B, int m0, int n0, int c, int buf)
{
    const uint32_t kb = SM_BUF + (uint32_t)buf * 32768u;
    const int k0 = c << 6;
    #pragma unroll
    for (int r = 0; r < 4; ++r) {
        const int u = r * 256 + tid;        // 0..1023
        const int row = u >> 3, c16 = u & 7;
        const uint32_t so = (uint32_t)(row * 128 + ((c16 * 16) ^ ((row & 7) << 4)));
        CP_ASYNC16(sb + kb + so,
                   (const char*)(A + (size_t)(m0 + row) * 768 + k0 + c16 * 8));
        CP_ASYNC16(sb + kb + 16384 + so,
                   (const char*)(B + (size_t)(n0 + row) * 768 + k0 + c16 * 8));
    }
}

__global__ __launch_bounds__(256, 2) void gemm_qkv(const float* __restrict__ bq,
                                                   const float* __restrict__ bk,
                                                   const float* __restrict__ bv) {
    extern __shared__ __align__(1024) char smem[];
    const int z = blockIdx.z;
    const float* bias = (z == 0) ? bq : (z == 1) ? bk : bv;
    __half* dst = (z == 0) ? g_q : (z == 1) ? g_k : g_v;
    const float oscale = (z == 0) ? SCL : 1.0f;
    const __half* A = g_in[z];
    const __half* B = g_w[z];
    const int m0 = blockIdx.x << 7;
    const int n0 = blockIdx.y << 7;

    const int tid = threadIdx.x;
    const int wid = tid >> 5;
    const int lid = tid & 31;
    const uint32_t sb = smem_u32(smem);

    if (tid < 32)
        ((float4*)(smem + SM_BIAS))[tid] = ((const float4*)(bias + n0))[tid];

    gemm_load_chunk(sb, tid, A, B, m0, n0, 0, 0);
    CP_COMMIT();

    float acc[2][8][4];
    #pragma unroll
    for (int mt = 0; mt < 2; ++mt)
        #pragma unroll
        for (int nt = 0; nt < 8; ++nt)
            #pragma unroll
            for (int e = 0; e < 4; ++e) acc[mt][nt][e] = 0.f;

    const int wm = (wid >> 1) << 5;     // 0/32/64/96
    const int wn = (wid & 1) << 6;      // 0/64
    const int lq = lid >> 3;
    const int lr = lid & 7;

    for (int c = 0; c < 12; ++c) {
        CP_WAIT0();
        __syncthreads();
        if (c < 11) {
            gemm_load_chunk(sb, tid, A, B, m0, n0, c + 1, (c + 1) & 1);
            CP_COMMIT();
        }
        const uint32_t kb = SM_BUF + (uint32_t)(c & 1) * 32768u;

        #pragma unroll
        for (int ks = 0; ks < 4; ++ks) {
            uint32_t ah[2][4];
            #pragma unroll
            for (int mt = 0; mt < 2; ++mt) {
                const int row = wm + mt * 16 + ((lq & 1) << 3) + lr;
                const int kc  = (ks << 4) + ((lq >> 1) << 3);
                const uint32_t off = (uint32_t)(row * 128 + ((kc * 2) ^ ((row & 7) << 4)));
                LDSM_X4(ah[mt][0], ah[mt][1], ah[mt][2], ah[mt][3], sb + kb + off);
            }
            uint32_t bh[8][2];
            #pragma unroll
            for (int nf = 0; nf < 4; ++nf) {
                const int nrow = wn + nf * 16 + ((lq >> 1) << 3) + lr;
                const int kc   = (ks << 4) + ((lq & 1) << 3);
                const uint32_t off = (uint32_t)(nrow * 128 + ((kc * 2) ^ ((nrow & 7) << 4)));
                uint32_t t0, t1, t2, t3;
                LDSM_X4(t0, t1, t2, t3, sb + kb + 16384 + off);
                bh[nf * 2][0] = t0;     bh[nf * 2][1] = t1;
                bh[nf * 2 + 1][0] = t2; bh[nf * 2 + 1][1] = t3;
            }
            #pragma unroll
            for (int mt = 0; mt < 2; ++mt)
                #pragma unroll
                for (int nt = 0; nt < 8; ++nt)
                    MMA_F16(acc[mt][nt], ah[mt], bh[nt]);
        }
    }

    const int gID = lid >> 2;
    const int tc  = (lid & 3) << 1;
    const float* bs = (const float*)(smem + SM_BIAS);
    #pragma unroll
    for (int mt = 0; mt < 2; ++mt)
        #pragma unroll
        for (int nt = 0; nt < 8; ++nt) {
            const int colr = wn + nt * 8 + tc;
            const float b0 = bs[colr], b1 = bs[colr + 1];
            #pragma unroll
            for (int rh = 0; rh < 2; ++rh) {
                const int m = m0 + wm + mt * 16 + gID + rh * 8;
                float rx = (acc[mt][nt][rh * 2 + 0] + b0) * oscale;
                float ry = (acc[mt][nt][rh * 2 + 1] + b1) * oscale;
                const int b = m >> 11;
                const int s = m & 2047;
                const int head = (n0 + colr) >> 6;
                const int dh   = (n0 + colr) & 63;
                const size_t o = ((size_t)((b * 12 + head) << 11) + s) * 64 + dh;
                *(__half2*)(dst + o) = __floats2half2_rn(rx, ry);
            }
        }
}

// ---------------------------------------------------------------------------
// OUT GEMM: CTA 64x128, 128 threads, 4 warps of 32x64, occ 4. (20.1us)
// ---------------------------------------------------------------------------
#define SO_BIAS 0
#define SO_BUF  1024                  // + buf*24576 : A 8K + B 16K
#define SO_TOT  (1024 + 2 * 24576)    // 50176

__device__ __forceinline__ void out_load_chunk(uint32_t sb, int tid,
                                               int m0, int n0, int c, int buf)
{
    const uint32_t kb = SO_BUF + (uint32_t)buf * 24576u;
    const int k0 = c << 6;
    #pragma unroll
    for (int r = 0; r < 4; ++r) {       // A: 64 rows x 8 units = 512
        const int u = r * 128 + tid;
        const int row = u >> 3, c16 = u & 7;
        const uint32_t so = (uint32_t)(row * 128 + ((c16 * 16) ^ ((row & 7) << 4)));
        CP_ASYNC16(sb + kb + so,
                   (const char*)(g_att + (size_t)(m0 + row) * 768 + k0 + c16 * 8));
    }
    #pragma unroll
    for (int r = 0; r < 8; ++r) {       // B: 128 rows x 8 units = 1024
        const int u = r * 128 + tid;
        const int row = u >> 3, c16 = u & 7;
        const uint32_t so = (uint32_t)(row * 128 + ((c16 * 16) ^ ((row & 7) << 4)));
        CP_ASYNC16(sb + kb + 8192 + so,
                   (const char*)(g_w[3] + (size_t)(n0 + row) * 768 + k0 + c16 * 8));
    }
}

__global__ __launch_bounds__(128, 4) void gemm_out(const float* __restrict__ bo,
                                                   float* __restrict__ out)
{
    extern __shared__ __align__(1024) char smem[];
    const int m0 = blockIdx.x << 6;
    const int n0 = blockIdx.y << 7;
    const int tid = threadIdx.x;
    const int wid = tid >> 5;
    const int lid = tid & 31;
    const uint32_t sb = smem_u32(smem);

    if (tid < 32)
        ((float4*)(smem + SO_BIAS))[tid] = ((const float4*)(bo + n0))[tid];

    out_load_chunk(sb, tid, m0, n0, 0, 0);
    CP_COMMIT();

    float acc[2][8][4];
    #pragma unroll
    for (int mt = 0; mt < 2; ++mt)
        #pragma unroll
        for (int nt = 0; nt < 8; ++nt)
            #pragma unroll
            for (int e = 0; e < 4; ++e) acc[mt][nt][e] = 0.f;

    const int wm = (wid >> 1) << 5;     // 0/32
    const int wn = (wid & 1) << 6;      // 0/64
    const int lq = lid >> 3;
    const int lr = lid & 7;

    for (int c = 0; c < 12; ++c) {
        CP_WAIT0();
        __syncthreads();
        if (c < 11) {
            out_load_chunk(sb, tid, m0, n0, c + 1, (c + 1) & 1);
            CP_COMMIT();
        }
        const uint32_t kb = SO_BUF + (uint32_t)(c & 1) * 24576u;

        #pragma unroll
        for (int ks = 0; ks < 4; ++ks) {
            uint32_t ah[2][4];
            #pragma unroll
            for (int mt = 0; mt < 2; ++mt) {
                const int row = wm + mt * 16 + ((lq & 1) << 3) + lr;
                const int kc  = (ks << 4) + ((lq >> 1) << 3);
                const uint32_t off = (uint32_t)(row * 128 + ((kc * 2) ^ ((row & 7) << 4)));
                LDSM_X4(ah[mt][0], ah[mt][1], ah[mt][2], ah[mt][3], sb + kb + off);
            }
            uint32_t bh[8][2];
            #pragma unroll
            for (int nf = 0; nf < 4; ++nf) {
                const int nrow = wn + nf * 16 + ((lq >> 1) << 3) + lr;
                const int kc   = (ks << 4) + ((lq & 1) << 3);
                const uint32_t off = (uint32_t)(nrow * 128 + ((kc * 2) ^ ((nrow & 7) << 4)));
                uint32_t t0, t1, t2, t3;
                LDSM_X4(t0, t1, t2, t3, sb + kb + 8192 + off);
                bh[nf * 2][0] = t0;     bh[nf * 2][1] = t1;
                bh[nf * 2 + 1][0] = t2; bh[nf * 2 + 1][1] = t3;
            }
            #pragma unroll
            for (int mt = 0; mt < 2; ++mt)
                #pragma unroll
                for (int nt = 0; nt < 8; ++nt)
                    MMA_F16(acc[mt][nt], ah[mt], bh[nt]);
        }
    }

    const int gID = lid >> 2;
    const int tc  = (lid & 3) << 1;
    const float* bs = (const float*)(smem + SO_BIAS);
    #pragma unroll
    for (int mt = 0; mt < 2; ++mt)
        #pragma unroll
        for (int nt = 0; nt < 8; ++nt) {
            const int colr = wn + nt * 8 + tc;
            const float b0 = bs[colr], b1 = bs[colr + 1];
            #pragma unroll
            for (int rh = 0; rh < 2; ++rh) {
                const int m = m0 + wm + mt * 16 + gID + rh * 8;
                float rx = acc[mt][nt][rh * 2 + 0] + b0;
                float ry = acc[mt][nt][rh * 2 + 1] + b1;
                *(float2*)&out[(size_t)m * 768 + n0 + colr] = make_float2(rx, ry);
            }
        }
}

// ---------------------------------------------------------------------------
// Flash attention on HMMA (fp16, fp32 accum). EXACT R13/R15 body.
// CTA: 128 q-rows; 4 warps x 32 rows. Key tiles of 64, double-buffered K/V.
// S init from pre-scaled mask; P via ex2.approx.f16x2; l via ones-MMA.
// 48KB smem, 3 CTAs/SM.
// ---------------------------------------------------------------------------
#define FS_Q   0                     // 16KB: 128 rows x 128B
#define FS_KV  16384                 // + buf*16384 : K 8KB + V 8KB
#define FS_TOT (16384 + 2 * 16384)   // 49152

__device__ __forceinline__ void fa_load_tile(uint32_t sb, int tid, size_t base,
                                             int t, int buf) {
    const uint32_t kb = FS_KV + (uint32_t)buf * 16384u;
    const int s0 = t << 6;
    #pragma unroll
    for (int r = 0; r < 4; ++r) {
        const int u = r * 128 + tid;        // 0..511
        const int row = u >> 3, c16 = u & 7;
        const uint32_t so = (uint32_t)(row * 128 + ((c16 * 16) ^ ((row & 7) << 4)));
        const size_t g = base + (size_t)(s0 + row) * 64 + c16 * 8;
        CP_ASYNC16(sb + kb + so,        (const char*)(g_k + g));
        CP_ASYNC16(sb + kb + 8192 + so, (const char*)(g_v + g));
    }
}

__global__ __launch_bounds__(128, 3) void flash_mma()
{
    extern __shared__ __align__(1024) char smem[];
    const uint32_t sb = smem_u32(smem);
    const int tid = threadIdx.x;
    const int wid = tid >> 5;             // 0..3
    const int lid = tid & 31;
    const int lq  = lid >> 3;
    const int lr  = lid & 7;
    const int q0  = blockIdx.x << 7;      // 128 q-rows per CTA
    const int bh  = blockIdx.y;
    const size_t base = (size_t)bh * SS * SDH;

    // prologue: Q tile (128 rows) + KV tile 0
    #pragma unroll
    for (int r = 0; r < 8; ++r) {
        const int u = r * 128 + tid;      // 0..1023
        const int row = u >> 3, c16 = u & 7;
        const uint32_t so = (uint32_t)(row * 128 + ((c16 * 16) ^ ((row & 7) << 4)));
        CP_ASYNC16(sb + FS_Q + so,
                   (const char*)(g_q + base + (size_t)(q0 + row) * 64 + c16 * 8));
    }
    fa_load_tile(sb, tid, base, 0, 0);
    CP_COMMIT();

    // all-ones fp16 B fragment (1.0h = 0x3C00) for the row-sum MMA
    const uint32_t ones[2] = {0x3C003C00u, 0x3C003C00u};

    float ol[2][4];                       // row-sum accumulators (every col = l)
    float o[2][8][4];
    #pragma unroll
    for (int mt = 0; mt < 2; ++mt) {
        #pragma unroll
        for (int e = 0; e < 4; ++e) ol[mt][e] = 0.f;
        #pragma unroll
        for (int d = 0; d < 8; ++d)
            #pragma unroll
            for (int e = 0; e < 4; ++e) o[mt][d][e] = 0.f;
    }

    const int rA = q0 + (wid << 5) + (lid >> 2);

    for (int t = 0; t < 32; ++t) {
        CP_WAIT0();
        __syncthreads();

        if (t < 31) {
            fa_load_tile(sb, tid, base, t + 1, (t + 1) & 1);
            CP_COMMIT();
        }

        const uint32_t kb = FS_KV + (uint32_t)(t & 1) * 16384u;

        // ---- init S from pre-scaled mask (LDGs issued before MMA chain) ----
        float s_[2][8][4];
        {
            const __half* mk0 = g_mask + (size_t)rA * SS + (t << 6) + ((lid & 3) << 1);
            #pragma unroll
            for (int mt = 0; mt < 2; ++mt) {
                const __half* mlo = mk0 + (size_t)(mt << 4) * SS;
                const __half* mhi = mlo + (size_t)8 * SS;
                #pragma unroll
                for (int nt = 0; nt < 8; ++nt) {
                    float2 ma = __half22float2(*(const __half2*)(mlo + nt * 8));
                    float2 mb = __half22float2(*(const __half2*)(mhi + nt * 8));
                    s_[mt][nt][0] = ma.x; s_[mt][nt][1] = ma.y;
                    s_[mt][nt][2] = mb.x; s_[mt][nt][3] = mb.y;
                }
            }
        }

        // ---- S += Q' K^T (q pre-scaled), 64 keys, 2 m-tiles per warp ----
        #pragma unroll
        for (int ks = 0; ks < 4; ++ks) {
            uint32_t qf[2][4];
            #pragma unroll
            for (int mt = 0; mt < 2; ++mt) {
                const int row = (wid << 5) + (mt << 4) + ((lq & 1) << 3) + lr;
                const int kc  = (ks << 4) + ((lq >> 1) << 3);
                const uint32_t off = (uint32_t)(row * 128 + ((kc * 2) ^ ((row & 7) << 4)));
                LDSM_X4(qf[mt][0], qf[mt][1], qf[mt][2], qf[mt][3], sb + FS_Q + off);
            }
            #pragma unroll
            for (int hf = 0; hf < 4; ++hf) {
                const int nrow = (hf << 4) + ((lq >> 1) << 3) + lr;
                const int kc   = (ks << 4) + ((lq & 1) << 3);
                const uint32_t off = (uint32_t)(nrow * 128 + ((kc * 2) ^ ((nrow & 7) << 4)));
                uint32_t a0, a1, a2, a3;
                LDSM_X4(a0, a1, a2, a3, sb + kb + off);
                uint32_t k0[2] = {a0, a1}, k1[2] = {a2, a3};
                MMA_F16(s_[0][hf * 2],     qf[0], k0);
                MMA_F16(s_[0][hf * 2 + 1], qf[0], k1);
                MMA_F16(s_[1][hf * 2],     qf[1], k0);
                MMA_F16(s_[1][hf * 2 + 1], qf[1], k1);
            }
        }

        // ---- O += P V ; l += P * 1. P = ex2.f16x2(pack(s)) ----
        #pragma unroll
        for (int ks = 0; ks < 4; ++ks) {
            uint32_t ph0[4], ph1[4];
            ph0[0] = hexp2_pack(s_[0][2 * ks][0],     s_[0][2 * ks][1]);
            ph0[1] = hexp2_pack(s_[0][2 * ks][2],     s_[0][2 * ks][3]);
            ph0[2] = hexp2_pack(s_[0][2 * ks + 1][0], s_[0][2 * ks + 1][1]);
            ph0[3] = hexp2_pack(s_[0][2 * ks + 1][2], s_[0][2 * ks + 1][3]);
            ph1[0] = hexp2_pack(s_[1][2 * ks][0],     s_[1][2 * ks][1]);
            ph1[1] = hexp2_pack(s_[1][2 * ks][2],     s_[1][2 * ks][3]);
            ph1[2] = hexp2_pack(s_[1][2 * ks + 1][0], s_[1][2 * ks + 1][1]);
            ph1[3] = hexp2_pack(s_[1][2 * ks + 1][2], s_[1][2 * ks + 1][3]);

            MMA_F16(ol[0], ph0, ones);
            MMA_F16(ol[1], ph1, ones);

            #pragma unroll
            for (int dp = 0; dp < 4; ++dp) {
                const int j = (ks << 4) + ((lq & 1) << 3) + lr;
                const int d = (dp << 4) + ((lq >> 1) << 3);
                const uint32_t off = (uint32_t)(j * 128 + ((d * 2) ^ ((j & 7) << 4)));
                uint32_t v0, v1, v2, v3;
                LDSM_X4_T(v0, v1, v2, v3, sb + kb + 8192 + off);
                uint32_t vf0[2] = {v0, v1}, vf1[2] = {v2, v3};
                MMA_F16(o[0][dp * 2],     ph0, vf0);
                MMA_F16(o[0][dp * 2 + 1], ph0, vf1);
                MMA_F16(o[1][dp * 2],     ph1, vf0);
                MMA_F16(o[1][dp * 2 + 1], ph1, vf1);
            }
        }
    }

    // ---- epilogue: normalize by ones-MMA row sums, fp16 store ----
    const int b = bh / 12;
    const int h = bh % 12;
    #pragma unroll
    for (int mt = 0; mt < 2; ++mt) {
        const float inv0 = 1.f / ol[mt][0];   // rows r: every col equals l
        const float inv1 = 1.f / ol[mt][2];   // rows r+8
        const int s0 = q0 + (wid << 5) + (mt << 4) + (lid >> 2);
        const int s1 = s0 + 8;
        #pragma unroll
        for (int dp = 0; dp < 8; ++dp) {
            const int d = dp * 8 + ((lid & 3) << 1);
            const size_t oa = ((size_t)(b * SS + s0)) * SD + h * 64 + d;
            const size_t ob = ((size_t)(b * SS + s1)) * SD + h * 64 + d;
            *(__half2*)(g_att + oa) =
                __floats2half2_rn(o[mt][dp][0] * inv0, o[mt][dp][1] * inv0);
            *(__half2*)(g_att + ob) =
                __floats2half2_rn(o[mt][dp][2] * inv1, o[mt][dp][3] * inv1);
        }
    }
}

// ---------------------------------------------------------------------------
extern "C" void kernel_launch(void* const* d_in, const int* in_sizes, int n_in,
                              void* d_out, int out_size)
{
    const float* q    = (const float*)d_in[0];
    const float* k    = (const float*)d_in[1];
    const float* v    = (const float*)d_in[2];
    const float* mask = (const float*)d_in[3];
    const float* Wq   = (const float*)d_in[4];
    const float* bq   = (const float*)d_in[5];
    const float* Wk   = (const float*)d_in[6];
    const float* bk   = (const float*)d_in[7];
    const float* Wv   = (const float*)d_in[8];
    const float* bv   = (const float*)d_in[9];
    const float* Wo   = (const float*)d_in[10];
    const float* bo   = (const float*)d_in[11];
    float* out = (float*)d_out;

    (void)in_sizes; (void)n_in; (void)out_size;

    cudaFuncSetAttribute(gemm_qkv, cudaFuncAttributeMaxDynamicSharedMemorySize, SM_TOT);
    cudaFuncSetAttribute(gemm_out, cudaFuncAttributeMaxDynamicSharedMemorySize, SO_TOT);
    cudaFuncSetAttribute(flash_mma, cudaFuncAttributeMaxDynamicSharedMemorySize, FS_TOT);

    // conversion: 16 elems/thread, MLP=4 (3904 blocks)
    conv_all<<<3904, 256>>>(q, k, v, Wq, Wk, Wv, Wo, mask);

    // QKV: R15 128x128 version (R16's 64x128 regressed: doubled B traffic)
    gemm_qkv<<<dim3(32, 6, 3), 256, SM_TOT>>>(bq, bk, bv);
    flash_mma<<<dim3(SS / 128, SB * SH), 128, FS_TOT>>>();
    gemm_out<<<dim3(64, 6), 128, SO_TOT>>>(bo, out);
}